// round 15
// baseline (speedup 1.0000x reference)
#include <cuda_runtime.h>
#include <cuda_bf16.h>
#include <cstdint>

// ---------------------------------------------------------------------------
// Problem constants
// ---------------------------------------------------------------------------
static constexpr int NE    = 32;    // experts
static constexpr int NH    = 512;   // hidden
static constexpr int NI    = 1024;  // intermediate
static constexpr int NT    = 4096;  // tokens
static constexpr int NCAP  = 512;   // per-expert capacity
static constexpr int NFLAT = 8192;  // T*K

// ---------------------------------------------------------------------------
// Device scratch (allocation-free: __device__ globals)
// ---------------------------------------------------------------------------
__device__ int      g_cnt[NE];
__device__ int      g_rows[NE * NCAP];
// bf16 hi/lo planes (pre-converted operands)
__device__ uint16_t g_hid_h[NT * NH],            g_hid_l[NT * NH];
__device__ uint16_t g_gup_h[NE * 2 * NI * NH],   g_gup_l[NE * 2 * NI * NH];
__device__ uint16_t g_dwn_h[NE * NH * NI],       g_dwn_l[NE * NH * NI];
__device__ uint16_t g_act_h[NE * NCAP * NI],     g_act_l[NE * NCAP * NI];

// ---------------------------------------------------------------------------
// SMEM: 3 pipeline stages; each stage = 4 tiles of 128 rows x 32 bf16
// (64 B/row) = 8 KB per tile, 32 KB per stage, 96 KB total.
// ---------------------------------------------------------------------------
static constexpr int T_AHI = 0;
static constexpr int T_ALO = 8192;
static constexpr int T_BHI = 16384;
static constexpr int T_BLO = 24576;
static constexpr int STAGE_BYTES = 32768;
static constexpr int NSTAGE      = 3;
static constexpr int SMEM_BYTES  = NSTAGE * STAGE_BYTES;   // 98304

// ---------------------------------------------------------------------------
// PTX helpers (compute_103-legal: mma.sync + ldmatrix + cp.async)
// ---------------------------------------------------------------------------
__device__ __forceinline__ uint32_t smem_u32(const void* p) {
    uint32_t a;
    asm("{ .reg .u64 t; cvta.to.shared.u64 t, %1; cvt.u32.u64 %0, t; }"
        : "=r"(a) : "l"(p));
    return a;
}

__device__ __forceinline__ void ldsm4(uint32_t& r0, uint32_t& r1,
                                      uint32_t& r2, uint32_t& r3, uint32_t a) {
    asm volatile("ldmatrix.sync.aligned.m8n8.x4.shared.b16 {%0,%1,%2,%3}, [%4];"
                 : "=r"(r0), "=r"(r1), "=r"(r2), "=r"(r3) : "r"(a));
}

__device__ __forceinline__ void mma16816(float* d, const uint32_t* a,
                                         const uint32_t* b) {
    asm volatile(
        "mma.sync.aligned.m16n8k16.row.col.f32.bf16.bf16.f32 "
        "{%0,%1,%2,%3}, {%4,%5,%6,%7}, {%8,%9}, {%0,%1,%2,%3};"
        : "+f"(d[0]), "+f"(d[1]), "+f"(d[2]), "+f"(d[3])
        : "r"(a[0]), "r"(a[1]), "r"(a[2]), "r"(a[3]), "r"(b[0]), "r"(b[1]));
}

__device__ __forceinline__ void cp16(uint32_t dst, const void* src, int sz) {
    asm volatile("cp.async.ca.shared.global [%0], [%1], 16, %2;"
                 :: "r"(dst), "l"(src), "r"(sz) : "memory");
}
#define CP_COMMIT() asm volatile("cp.async.commit_group;" ::: "memory")
#define CP_WAIT1()  asm volatile("cp.async.wait_group 1;" ::: "memory")

// 64B-row swizzle: xor 16B-chunk index (bits[4:5]) with row bits (off bits[7:8]).
// 8-row-aligned ldmatrix reads land on 8 distinct 16B slots -> conflict-free.
__device__ __forceinline__ uint32_t swz64(uint32_t off) {
    return off ^ ((off >> 3) & 0x30);
}

__device__ __forceinline__ float silu(float g) {
    return g / (1.0f + __expf(-g));
}

__device__ __forceinline__ void split1(float v, uint16_t& h, uint16_t& l) {
    __nv_bfloat16 hb = __float2bfloat16(v);
    h = (uint16_t)__bfloat16_as_ushort(hb);
    l = (uint16_t)__bfloat16_as_ushort(__float2bfloat16(v - __bfloat162float(hb)));
}

// Consume one staged K=32 chunk: 2 k-steps, split-bf16 (hh + hl + lh) MMAs.
// Warp (wm, wn) owns a 64x32 subtile of the 128x128 CTA tile.
__device__ __forceinline__ void mma_chunk(uint32_t st, int lane, int wm, int wn,
                                          float acc[4][4][4]) {
    int a_row = wm * 64 + (lane & 7) + ((lane >> 3) & 1) * 8;
    int a_kh  = (lane >> 4) & 1;
    int b_row = wn * 32 + (lane & 7) + ((lane >> 4) & 1) * 8;
    int b_kh  = (lane >> 3) & 1;
#pragma unroll
    for (int ks = 0; ks < 2; ks++) {
        uint32_t bh[8], bl[8];
#pragma unroll
        for (int nb = 0; nb < 2; nb++) {
            uint32_t sw = swz64((uint32_t)((b_row + nb * 16) * 64 + (ks * 16 + b_kh * 8) * 2));
            ldsm4(bh[nb*4+0], bh[nb*4+1], bh[nb*4+2], bh[nb*4+3], st + T_BHI + sw);
            ldsm4(bl[nb*4+0], bl[nb*4+1], bl[nb*4+2], bl[nb*4+3], st + T_BLO + sw);
        }
#pragma unroll
        for (int mi = 0; mi < 4; mi++) {
            uint32_t sw = swz64((uint32_t)((a_row + mi * 16) * 64 + (ks * 16 + a_kh * 8) * 2));
            uint32_t ah[4], al[4];
            ldsm4(ah[0], ah[1], ah[2], ah[3], st + T_AHI + sw);
            ldsm4(al[0], al[1], al[2], al[3], st + T_ALO + sw);
#pragma unroll
            for (int ni = 0; ni < 4; ni++) {
                const uint32_t* bph = &bh[(ni >> 1) * 4 + (ni & 1) * 2];
                const uint32_t* bpl = &bl[(ni >> 1) * 4 + (ni & 1) * 2];
                mma16816(acc[mi][ni], ah, bph);
                mma16816(acc[mi][ni], ah, bpl);
                mma16816(acc[mi][ni], al, bph);
            }
        }
    }
}

// ---------------------------------------------------------------------------
// Kernel 0: zero output
// ---------------------------------------------------------------------------
__global__ void k_zero(float* __restrict__ out) {
    out[(size_t)blockIdx.x * blockDim.x + threadIdx.x] = 0.0f;
}

// ---------------------------------------------------------------------------
// Kernel C: fp32 -> bf16 hi/lo plane conversion (flat, vectorized)
// ---------------------------------------------------------------------------
__global__ void k_cvt(const float4* __restrict__ s, ushort4* __restrict__ dh,
                      ushort4* __restrict__ dl) {
    size_t i = (size_t)blockIdx.x * blockDim.x + threadIdx.x;
    float4 v = s[i];
    ushort4 h, l;
    split1(v.x, h.x, l.x);
    split1(v.y, h.y, l.y);
    split1(v.z, h.z, l.z);
    split1(v.w, h.w, l.w);
    dh[i] = h;
    dl[i] = l;
}

// ---------------------------------------------------------------------------
// Kernel 1: routing — per-expert block, ballot prefix-scan over flat slots.
// Matches the reference's cumsum-based Switch dispatch (pos >= CAP dropped).
// Index dtype auto-detected (JAX x64-disabled materializes int32).
// ---------------------------------------------------------------------------
__global__ void k_route(const int* __restrict__ idx32) {
    int e   = blockIdx.x;
    int tid = threadIdx.x;
    int w   = tid >> 5;
    int l   = tid & 31;

    int nz = 0;
    for (int i = tid; i < NFLAT / 2; i += 256) nz |= idx32[2 * i + 1];
    int is32 = __syncthreads_or(nz);
    int stride = is32 ? 1 : 2;

    __shared__ int warp_tot[8];
    int base = 0;
    for (int it = 0; it < NFLAT / 256; it++) {
        int i  = it * 256 + tid;
        int ei = idx32[i * stride];
        bool flag = (ei == e);
        unsigned m = __ballot_sync(0xffffffffu, flag);
        int wpre = __popc(m & ((1u << l) - 1u));
        if (l == 0) warp_tot[w] = __popc(m);
        __syncthreads();
        int wbase = 0;
#pragma unroll
        for (int j = 0; j < 8; j++) if (j < w) wbase += warp_tot[j];
        int tot = 0;
#pragma unroll
        for (int j = 0; j < 8; j++) tot += warp_tot[j];
        int pos = base + wbase + wpre;
        if (flag && pos < NCAP) g_rows[e * NCAP + pos] = i;
        base += tot;
        __syncthreads();
    }
    if (tid == 0) g_cnt[e] = (base > NCAP) ? NCAP : base;
}

// ---------------------------------------------------------------------------
// cp.async stage issue: 8 granules of 16B per thread per chunk.
// Per-thread (src base, dst offset, size) precomputed; per chunk add k0*2B.
// ---------------------------------------------------------------------------
struct StagePlan {
    const char* src[8];
    uint32_t    dst[8];
    int         sz[8];
};

__device__ __forceinline__ void issue_stage(uint32_t stage_base, const StagePlan& pl,
                                            int koff) {
#pragma unroll
    for (int i = 0; i < 8; i++)
        cp16(stage_base + pl.dst[i], pl.src[i] + koff, pl.sz[i]);
}

// ---------------------------------------------------------------------------
// Kernel 2: GEMM1 + SwiGLU.  Per CTA: expert e, m-tile (128 rows), n-pair p.
// D[128 x 128] = X[128 x 512] * W^T.  B rows interleave gate/up (even=gate,
// odd=up).  3-stage cp.async pipeline, one barrier per chunk.
// ---------------------------------------------------------------------------
__global__ __launch_bounds__(256, 2)
void k_gemm1() {
    int b   = blockIdx.x;
    int e   = b >> 6;
    int rem = b & 63;
    int mt  = rem >> 4;
    int p   = rem & 15;
    int cnt = g_cnt[e];
    int row0 = mt * 128;
    if (row0 >= cnt) return;

    extern __shared__ char smem[];
    uint32_t sb = smem_u32(smem);
    int tid = threadIdx.x, lane = tid & 31, wid = tid >> 5;
    int wm = wid & 1, wn = wid >> 1;

    // Per-thread copy plan: granule g = tid + i*256 -> (tile, row, quarter)
    StagePlan pl;
#pragma unroll
    for (int i = 0; i < 8; i++) {
        int g    = tid + i * 256;
        int tile = g >> 9;
        int r    = (g >> 2) & 127;
        int q    = g & 3;
        pl.dst[i] = (uint32_t)(tile * 8192) + swz64((uint32_t)(r * 64 + q * 16));
        int sz = 16;
        const char* s;
        if (tile < 2) {                      // A: gathered token rows
            int mr = row0 + r;
            if (mr < cnt) {
                int f = g_rows[e * NCAP + mr];
                const uint16_t* plane = (tile == 0) ? g_hid_h : g_hid_l;
                s = (const char*)(plane + (size_t)(f >> 1) * NH) + q * 16;
            } else {
                s = (const char*)g_hid_h;    // unused (zero-fill)
                sz = 0;
            }
        } else {                             // B: interleaved gate/up rows
            int gr = ((r & 1) == 0) ? (p * 64 + (r >> 1))
                                    : (NI + p * 64 + (r >> 1));
            const uint16_t* plane = (tile == 2) ? g_gup_h : g_gup_l;
            s = (const char*)(plane + ((size_t)e * 2 * NI + gr) * NH) + q * 16;
        }
        pl.src[i] = s;
        pl.sz[i]  = sz;
    }

    float acc[4][4][4];
#pragma unroll
    for (int mi = 0; mi < 4; mi++)
#pragma unroll
        for (int ni = 0; ni < 4; ni++)
#pragma unroll
            for (int q = 0; q < 4; q++) acc[mi][ni][q] = 0.0f;

    constexpr int NC = NH / 32;  // 16 chunks; k-offset in bytes = chunk*64
    issue_stage(sb + 0 * STAGE_BYTES, pl, 0);  CP_COMMIT();
    issue_stage(sb + 1 * STAGE_BYTES, pl, 64); CP_COMMIT();

#pragma unroll 1
    for (int c = 0; c < NC; c++) {
        CP_WAIT1();
        __syncthreads();
        if (c + 2 < NC) {
            issue_stage(sb + ((c + 2) % NSTAGE) * STAGE_BYTES, pl, (c + 2) * 64);
            CP_COMMIT();
        }
        mma_chunk(sb + (c % NSTAGE) * STAGE_BYTES, lane, wm, wn, acc);
    }

    // Epilogue: act[m, p*64 + c] = silu(gate_c) * up_c  -> bf16 hi/lo planes
    int g = lane >> 2, q = lane & 3;
#pragma unroll
    for (int mi = 0; mi < 4; mi++) {
        int m0 = row0 + wm * 64 + mi * 16 + g;
        size_t i0 = ((size_t)e * NCAP + m0) * NI;
        size_t i8 = i0 + (size_t)8 * NI;
#pragma unroll
        for (int ni = 0; ni < 4; ni++) {
            int cc = p * 64 + wn * 16 + ni * 4 + q;
            uint16_t h, l;
            split1(silu(acc[mi][ni][0]) * acc[mi][ni][1], h, l);
            g_act_h[i0 + cc] = h; g_act_l[i0 + cc] = l;
            split1(silu(acc[mi][ni][2]) * acc[mi][ni][3], h, l);
            g_act_h[i8 + cc] = h; g_act_l[i8 + cc] = l;
        }
    }
}

// ---------------------------------------------------------------------------
// Kernel 3: GEMM2 + weighted scatter.  Per CTA: expert e, m-tile, h-tile(128).
// Y[128 x 128] = act[128 x 1024] * down^T; out[t, h0+j] += w * y (atomic).
// ---------------------------------------------------------------------------
__global__ __launch_bounds__(256, 2)
void k_gemm2(const float* __restrict__ wts, float* __restrict__ out) {
    int b   = blockIdx.x;
    int e   = b >> 4;
    int rem = b & 15;
    int mt  = rem >> 2;
    int ht  = rem & 3;
    int cnt = g_cnt[e];
    int row0 = mt * 128;
    if (row0 >= cnt) return;
    int h0 = ht * 128;

    extern __shared__ char smem[];
    uint32_t sb = smem_u32(smem);
    int tid = threadIdx.x, lane = tid & 31, wid = tid >> 5;
    int wm = wid & 1, wn = wid >> 1;

    StagePlan pl;
#pragma unroll
    for (int i = 0; i < 8; i++) {
        int g    = tid + i * 256;
        int tile = g >> 9;
        int r    = (g >> 2) & 127;
        int q    = g & 3;
        pl.dst[i] = (uint32_t)(tile * 8192) + swz64((uint32_t)(r * 64 + q * 16));
        pl.sz[i]  = 16;
        if (tile < 2) {                      // A: activation rows
            const uint16_t* plane = (tile == 0) ? g_act_h : g_act_l;
            pl.src[i] = (const char*)(plane + ((size_t)e * NCAP + row0 + r) * NI) + q * 16;
        } else {                             // B: down-proj rows
            const uint16_t* plane = (tile == 2) ? g_dwn_h : g_dwn_l;
            pl.src[i] = (const char*)(plane + ((size_t)e * NH + h0 + r) * NI) + q * 16;
        }
    }

    float acc[4][4][4];
#pragma unroll
    for (int mi = 0; mi < 4; mi++)
#pragma unroll
        for (int ni = 0; ni < 4; ni++)
#pragma unroll
            for (int q = 0; q < 4; q++) acc[mi][ni][q] = 0.0f;

    constexpr int NC = NI / 32;  // 32 chunks
    issue_stage(sb + 0 * STAGE_BYTES, pl, 0);  CP_COMMIT();
    issue_stage(sb + 1 * STAGE_BYTES, pl, 64); CP_COMMIT();

#pragma unroll 1
    for (int c = 0; c < NC; c++) {
        CP_WAIT1();
        __syncthreads();
        if (c + 2 < NC) {
            issue_stage(sb + ((c + 2) % NSTAGE) * STAGE_BYTES, pl, (c + 2) * 64);
            CP_COMMIT();
        }
        mma_chunk(sb + (c % NSTAGE) * STAGE_BYTES, lane, wm, wn, acc);
    }

    // Epilogue: weighted atomic scatter to out[token]
    int g = lane >> 2, q = lane & 3;
#pragma unroll
    for (int mi = 0; mi < 4; mi++) {
        int m0 = row0 + wm * 64 + mi * 16 + g;
#pragma unroll
        for (int half = 0; half < 2; half++) {
            int m = m0 + half * 8;
            if (m < cnt) {
                int f   = g_rows[e * NCAP + m];
                float w = wts[f];
                float* op = out + (size_t)(f >> 1) * NH + h0;
#pragma unroll
                for (int ni = 0; ni < 4; ni++) {
                    int j = wn * 32 + ni * 8 + q * 2;
                    atomicAdd(op + j,     w * acc[mi][ni][half * 2 + 0]);
                    atomicAdd(op + j + 1, w * acc[mi][ni][half * 2 + 1]);
                }
            }
        }
    }
}

// ---------------------------------------------------------------------------
// Launch
// ---------------------------------------------------------------------------
extern "C" void kernel_launch(void* const* d_in, const int* in_sizes, int n_in,
                              void* d_out, int out_size) {
    (void)in_sizes; (void)n_in; (void)out_size;
    const float* hidden = (const float*)d_in[0];
    const int*   idx32  = (const int*)d_in[1];     // int32 OR int64 (auto-detected)
    const float* wts    = (const float*)d_in[2];
    const float* gup    = (const float*)d_in[3];
    const float* down   = (const float*)d_in[4];
    float*       out    = (float*)d_out;

    cudaFuncSetAttribute(k_gemm1, cudaFuncAttributeMaxDynamicSharedMemorySize, SMEM_BYTES);
    cudaFuncSetAttribute(k_gemm2, cudaFuncAttributeMaxDynamicSharedMemorySize, SMEM_BYTES);

    // Resolve device-global plane addresses (host side, graph-capturable)
    static ushort4 *hh = nullptr, *hl = nullptr, *guh = nullptr, *gul = nullptr,
                   *dwh = nullptr, *dwl = nullptr;
    if (!hh) {
        cudaGetSymbolAddress((void**)&hh,  g_hid_h);
        cudaGetSymbolAddress((void**)&hl,  g_hid_l);
        cudaGetSymbolAddress((void**)&guh, g_gup_h);
        cudaGetSymbolAddress((void**)&gul, g_gup_l);
        cudaGetSymbolAddress((void**)&dwh, g_dwn_h);
        cudaGetSymbolAddress((void**)&dwl, g_dwn_l);
    }

    k_zero<<<(NT * NH) / 256, 256>>>(out);
    k_route<<<NE, 256>>>(idx32);
    k_cvt<<<(NT * NH) / 1024, 256>>>((const float4*)hidden, hh, hl);
    k_cvt<<<(NE * 2 * NI * NH) / 1024, 256>>>((const float4*)gup, guh, gul);
    k_cvt<<<(NE * NH * NI) / 1024, 256>>>((const float4*)down, dwh, dwl);
    k_gemm1<<<NE * 4 * 16, 256, SMEM_BYTES>>>();
    k_gemm2<<<NE * 4 * 4, 256, SMEM_BYTES>>>(wts, out);
}